// round 15
// baseline (speedup 1.0000x reference)
#include <cuda_runtime.h>

// Problem constants (fixed by the dataset)
#define BB   256
#define NN   32
#define WW   1920
#define HH   1080
#define ROWS   (BB * NN)        // 8192 rows; one warp per row (x-row + y-row)
#define WPB    8                // warps per block
#define GRIDX  (ROWS / WPB)     // 1024 blocks
#define NSLOTS 32

// Scratch (__device__ globals; zero at load, reset by last block every launch
// so graph replays are deterministic).
__device__ float        g_accs[NSLOTS];
__device__ float        g_counts[NSLOTS];
__device__ unsigned int g_done;

__inline__ __device__ float warp_sum(float v) {
    #pragma unroll
    for (int o = 16; o > 0; o >>= 1)
        v += __shfl_xor_sync(0xffffffffu, v, o);
    return v;
}

// sum of clamp(log(1-p), -100) over a float4
__inline__ __device__ float l1term(float4 v) {
    return fmaxf(__logf(1.0f - v.x), -100.0f)
         + fmaxf(__logf(1.0f - v.y), -100.0f)
         + fmaxf(__logf(1.0f - v.z), -100.0f)
         + fmaxf(__logf(1.0f - v.w), -100.0f);
}

__global__ void __launch_bounds__(256)
hbdl_kernel(const float* __restrict__ px,
            const float* __restrict__ py,
            const long long* __restrict__ tgt,
            float* __restrict__ out) {
    const int tid  = threadIdx.x;
    const int lane = tid & 31;
    const int wid  = tid >> 5;
    const int r    = blockIdx.x * WPB + wid;    // row id, [0, 8192)

    const float* rowx = px + (size_t)r * WW;
    const float* rowy = py + (size_t)r * HH;

    // Kick off the tgt load (lane 0) but DON'T gate the stream on it —
    // stream unconditionally, apply the mask at the end.
    long long t0 = 0, t1 = 0;
    if (lane == 0) {
        longlong2 t2 = ((const longlong2*)tgt)[r];
        t0 = t2.x; t1 = t2.y;
    }

    // ---- unconditional stream, fully unrolled for max MLP ----
    // x-row: 480 float4 = 15 full warp-iterations
    float sx = 0.0f;
    {
        const float4* p4 = (const float4*)rowx;
        #pragma unroll
        for (int k = 0; k < 15; k++)
            sx += l1term(p4[k * 32 + lane]);
    }
    // y-row: 270 float4 = 8 full warp-iterations + 14-lane tail
    float sy = 0.0f;
    {
        const float4* p4 = (const float4*)rowy;
        #pragma unroll
        for (int k = 0; k < 8; k++)
            sy += l1term(p4[k * 32 + lane]);
        if (lane < 14)
            sy += l1term(p4[256 + lane]);
    }

    // combine with per-axis 1/L weights before the warp reduce
    float ws = warp_sum(sx * (1.0f / (float)WW) + sy * (1.0f / (float)HH));

    // ---- resolve mask/targets (tgt load has long since landed) ----
    int tx = __shfl_sync(0xffffffffu, (int)t0, 0);
    int ty = __shfl_sync(0xffffffffu, (int)t1, 0);
    tx = min(max(tx, 0), WW - 1);
    ty = min(max(ty, 0), HH - 1);
    const bool valid = !((tx == 0) && (ty == 0));   // warp-uniform

    float contrib = 0.0f;
    if (lane == 0 && valid) {
        // row loss: (-lp[t] - (sum_l1p - l1p[t])) / L , per axis
        float p = rowx[tx];
        float q = rowy[ty];
        contrib = -ws
                + (fmaxf(__logf(1.0f - p), -100.0f)
                 - fmaxf(__logf(p),        -100.0f)) * (1.0f / (float)WW)
                + (fmaxf(__logf(1.0f - q), -100.0f)
                 - fmaxf(__logf(q),        -100.0f)) * (1.0f / (float)HH);
        atomicAdd(&g_counts[blockIdx.x & (NSLOTS - 1)], 1.0f);
    }

    // --- block reduce (8 warps) -> one striped atomic per block ---
    __shared__ float sh[WPB];
    if (lane == 0) sh[wid] = contrib;
    __syncthreads();
    if (tid == 0) {
        float t = 0.0f;
        #pragma unroll
        for (int w = 0; w < WPB; w++) t += sh[w];
        atomicAdd(&g_accs[blockIdx.x & (NSLOTS - 1)], t);
    }

    // --- ticket: last block finalizes + resets scratch ---
    __shared__ bool isLast;
    if (tid == 0) {
        __threadfence();
        isLast = (atomicAdd(&g_done, 1u) == (unsigned)(GRIDX - 1));
    }
    __syncthreads();
    if (isLast && tid < NSLOTS) {
        volatile float* va = g_accs;
        volatile float* vc = g_counts;
        float a = va[tid];
        float c = vc[tid];
        a = warp_sum(a);
        c = warp_sum(c);
        if (tid == 0) {
            out[0] = a / fmaxf(c, 1.0f);
            g_done = 0u;
        }
        g_accs[tid]   = 0.0f;
        g_counts[tid] = 0.0f;
    }
}

extern "C" void kernel_launch(void* const* d_in, const int* in_sizes, int n_in,
                              void* d_out, int out_size) {
    const float*     px  = (const float*)d_in[0];       // [256,32,1920] f32
    const float*     py  = (const float*)d_in[1];       // [256,32,1080] f32
    const long long* tgt = (const long long*)d_in[2];   // [256,32,2] i64
    float* out = (float*)d_out;

    hbdl_kernel<<<GRIDX, 256>>>(px, py, tgt, out);
}

// round 16
// speedup vs baseline: 1.0035x; 1.0035x over previous
#include <cuda_runtime.h>

// Problem constants (fixed by the dataset)
#define BB   256
#define NN   32
#define WW   1920
#define HH   1080
#define ROWS   (BB * NN)        // 8192 rows; one warp per row (x-row + y-row)
#define WPB    8                // warps per block
#define GRIDX  (ROWS / WPB)     // 1024 blocks
#define NSLOTS 32

// Scratch (__device__ globals; zero at load, reset by last block every launch
// so graph replays are deterministic).
__device__ float        g_accs[NSLOTS];
__device__ float        g_counts[NSLOTS];
__device__ unsigned int g_done;

__inline__ __device__ float warp_sum(float v) {
    #pragma unroll
    for (int o = 16; o > 0; o >>= 1)
        v += __shfl_xor_sync(0xffffffffu, v, o);
    return v;
}

// sum of clamp(log(1-p), -100) over a float4
__inline__ __device__ float l1term(float4 v) {
    return fmaxf(__logf(1.0f - v.x), -100.0f)
         + fmaxf(__logf(1.0f - v.y), -100.0f)
         + fmaxf(__logf(1.0f - v.z), -100.0f)
         + fmaxf(__logf(1.0f - v.w), -100.0f);
}

__global__ void __launch_bounds__(256)
hbdl_kernel(const float* __restrict__ px,
            const float* __restrict__ py,
            const long long* __restrict__ tgt,
            float* __restrict__ out) {
    const int tid  = threadIdx.x;
    const int lane = tid & 31;
    const int wid  = tid >> 5;
    const int r    = blockIdx.x * WPB + wid;    // row id, [0, 8192)

    const float* rowx = px + (size_t)r * WW;
    const float* rowy = py + (size_t)r * HH;

    // Kick off the tgt load (lane 0) but DON'T gate the stream on it —
    // the load's latency overlaps the stream; mask is applied at the end.
    long long t0 = 0, t1 = 0;
    if (lane == 0) {
        longlong2 t2 = ((const longlong2*)tgt)[r];
        t0 = t2.x; t1 = t2.y;
    }

    // ---- unconditional stream, R14's proven load cadence ----
    // x-row: 480 float4 = 15 full warp-iterations, batched 5 deep (MLP~5)
    float sx = 0.0f;
    {
        const float4* p4 = (const float4*)rowx;
        #pragma unroll 5
        for (int k = 0; k < 15; k++)
            sx += l1term(p4[k * 32 + lane]);
    }
    // y-row: 270 float4 = 8 full warp-iterations + 14-lane tail
    float sy = 0.0f;
    {
        const float4* p4 = (const float4*)rowy;
        #pragma unroll
        for (int k = 0; k < 8; k++)
            sy += l1term(p4[k * 32 + lane]);
        if (lane < 14)
            sy += l1term(p4[256 + lane]);
    }

    // combine with per-axis 1/L weights before the warp reduce
    float ws = warp_sum(sx * (1.0f / (float)WW) + sy * (1.0f / (float)HH));

    // ---- resolve mask/targets (tgt load landed long ago) ----
    int tx = __shfl_sync(0xffffffffu, (int)t0, 0);
    int ty = __shfl_sync(0xffffffffu, (int)t1, 0);
    tx = min(max(tx, 0), WW - 1);
    ty = min(max(ty, 0), HH - 1);
    const bool valid = !((tx == 0) && (ty == 0));   // warp-uniform

    float contrib = 0.0f;
    if (lane == 0 && valid) {
        // row loss: (-lp[t] - (sum_l1p - l1p[t])) / L , per axis
        float p = rowx[tx];
        float q = rowy[ty];
        contrib = -ws
                + (fmaxf(__logf(1.0f - p), -100.0f)
                 - fmaxf(__logf(p),        -100.0f)) * (1.0f / (float)WW)
                + (fmaxf(__logf(1.0f - q), -100.0f)
                 - fmaxf(__logf(q),        -100.0f)) * (1.0f / (float)HH);
        atomicAdd(&g_counts[blockIdx.x & (NSLOTS - 1)], 1.0f);
    }

    // --- block reduce (8 warps) -> one striped atomic per block ---
    __shared__ float sh[WPB];
    if (lane == 0) sh[wid] = contrib;
    __syncthreads();
    if (tid == 0) {
        float t = 0.0f;
        #pragma unroll
        for (int w = 0; w < WPB; w++) t += sh[w];
        atomicAdd(&g_accs[blockIdx.x & (NSLOTS - 1)], t);
    }

    // --- ticket: last block finalizes + resets scratch ---
    __shared__ bool isLast;
    if (tid == 0) {
        __threadfence();
        isLast = (atomicAdd(&g_done, 1u) == (unsigned)(GRIDX - 1));
    }
    __syncthreads();
    if (isLast && tid < NSLOTS) {
        volatile float* va = g_accs;
        volatile float* vc = g_counts;
        float a = va[tid];
        float c = vc[tid];
        a = warp_sum(a);
        c = warp_sum(c);
        if (tid == 0) {
            out[0] = a / fmaxf(c, 1.0f);
            g_done = 0u;
        }
        g_accs[tid]   = 0.0f;
        g_counts[tid] = 0.0f;
    }
}

extern "C" void kernel_launch(void* const* d_in, const int* in_sizes, int n_in,
                              void* d_out, int out_size) {
    const float*     px  = (const float*)d_in[0];       // [256,32,1920] f32
    const float*     py  = (const float*)d_in[1];       // [256,32,1080] f32
    const long long* tgt = (const long long*)d_in[2];   // [256,32,2] i64
    float* out = (float*)d_out;

    hbdl_kernel<<<GRIDX, 256>>>(px, py, tgt, out);
}

// round 17
// speedup vs baseline: 1.2462x; 1.2419x over previous
#include <cuda_runtime.h>

// Problem constants (fixed by the dataset)
#define BB   256
#define NN   32
#define WW   1920
#define HH   1080
#define ROWS   (BB * NN)        // 8192 rows
#define RPW    2                // row-pairs (x+y) per warp
#define WPB    8                // warps per block
#define NWARP  (ROWS / RPW)     // 4096 warps
#define GRIDX  (NWARP / WPB)    // 512 blocks
#define NSLOTS 32

// Scratch (__device__ globals; zero at load, reset by last block every launch
// so graph replays are deterministic).
__device__ float        g_accs[NSLOTS];
__device__ float        g_counts[NSLOTS];
__device__ unsigned int g_done;

__inline__ __device__ float warp_sum(float v) {
    #pragma unroll
    for (int o = 16; o > 0; o >>= 1)
        v += __shfl_xor_sync(0xffffffffu, v, o);
    return v;
}

// sum of clamp(log(1-p), -100) over a float4
__inline__ __device__ float l1term(float4 v) {
    return fmaxf(__logf(1.0f - v.x), -100.0f)
         + fmaxf(__logf(1.0f - v.y), -100.0f)
         + fmaxf(__logf(1.0f - v.z), -100.0f)
         + fmaxf(__logf(1.0f - v.w), -100.0f);
}

// Process one (x-row, y-row) pair. The tgt-gated stream is intentional:
// the serialized L2-hot tgt load staggers warps' stream starts, which keeps
// the L1tex wavefront queue shallow (removing the gate measured 12.8 -> 18.4us).
// Returns lane-0-meaningful (sum-weighted) row contribution; adds to cnt.
__inline__ __device__ float row_pair(const float* __restrict__ px,
                                     const float* __restrict__ py,
                                     const long long* __restrict__ tgt,
                                     int r, int lane, float& cnt) {
    const float* rowx = px + (size_t)r * WW;
    const float* rowy = py + (size_t)r * HH;

    long long t0 = 0, t1 = 0;
    if (lane == 0) {
        longlong2 t2 = ((const longlong2*)tgt)[r];
        t0 = t2.x; t1 = t2.y;
    }
    int tx = __shfl_sync(0xffffffffu, (int)t0, 0);
    int ty = __shfl_sync(0xffffffffu, (int)t1, 0);
    tx = min(max(tx, 0), WW - 1);
    ty = min(max(ty, 0), HH - 1);
    const bool valid = !((tx == 0) && (ty == 0));   // warp-uniform

    float contrib = 0.0f;
    if (valid) {
        // x-row: 480 float4 = 15 warp-iterations, batched 5 deep (MLP~5)
        float sx = 0.0f;
        {
            const float4* p4 = (const float4*)rowx;
            #pragma unroll 5
            for (int k = 0; k < 15; k++)
                sx += l1term(p4[k * 32 + lane]);
        }
        // y-row: 270 float4 = 8 warp-iterations + 14-lane tail
        float sy = 0.0f;
        {
            const float4* p4 = (const float4*)rowy;
            #pragma unroll
            for (int k = 0; k < 8; k++)
                sy += l1term(p4[k * 32 + lane]);
            if (lane < 14)
                sy += l1term(p4[256 + lane]);
        }

        float ws = warp_sum(sx * (1.0f / (float)WW) + sy * (1.0f / (float)HH));

        if (lane == 0) {
            float p = rowx[tx];
            float q = rowy[ty];
            contrib = -ws
                    + (fmaxf(__logf(1.0f - p), -100.0f)
                     - fmaxf(__logf(p),        -100.0f)) * (1.0f / (float)WW)
                    + (fmaxf(__logf(1.0f - q), -100.0f)
                     - fmaxf(__logf(q),        -100.0f)) * (1.0f / (float)HH);
            cnt += 1.0f;
        }
    }
    return contrib;
}

__global__ void __launch_bounds__(256)
hbdl_kernel(const float* __restrict__ px,
            const float* __restrict__ py,
            const long long* __restrict__ tgt,
            float* __restrict__ out) {
    const int tid  = threadIdx.x;
    const int lane = tid & 31;
    const int wid  = tid >> 5;
    const int gw   = blockIdx.x * WPB + wid;    // warp id, [0, 4096)

    float cnt = 0.0f;
    float contrib = 0.0f;
    // Two rows per warp, ROWS/2 apart (different L2 regions).
    contrib += row_pair(px, py, tgt, gw,            lane, cnt);
    contrib += row_pair(px, py, tgt, gw + ROWS / 2, lane, cnt);

    if (lane == 0 && cnt != 0.0f)
        atomicAdd(&g_counts[blockIdx.x & (NSLOTS - 1)], cnt);

    // --- block reduce (8 warps) -> one striped atomic per block ---
    __shared__ float sh[WPB];
    if (lane == 0) sh[wid] = contrib;
    __syncthreads();
    if (tid == 0) {
        float t = 0.0f;
        #pragma unroll
        for (int w = 0; w < WPB; w++) t += sh[w];
        atomicAdd(&g_accs[blockIdx.x & (NSLOTS - 1)], t);
    }

    // --- ticket: last block finalizes + resets scratch ---
    __shared__ bool isLast;
    if (tid == 0) {
        __threadfence();
        isLast = (atomicAdd(&g_done, 1u) == (unsigned)(GRIDX - 1));
    }
    __syncthreads();
    if (isLast && tid < NSLOTS) {
        volatile float* va = g_accs;
        volatile float* vc = g_counts;
        float a = va[tid];
        float c = vc[tid];
        a = warp_sum(a);
        c = warp_sum(c);
        if (tid == 0) {
            out[0] = a / fmaxf(c, 1.0f);
            g_done = 0u;
        }
        g_accs[tid]   = 0.0f;
        g_counts[tid] = 0.0f;
    }
}

extern "C" void kernel_launch(void* const* d_in, const int* in_sizes, int n_in,
                              void* d_out, int out_size) {
    const float*     px  = (const float*)d_in[0];       // [256,32,1920] f32
    const float*     py  = (const float*)d_in[1];       // [256,32,1080] f32
    const long long* tgt = (const long long*)d_in[2];   // [256,32,2] i64
    float* out = (float*)d_out;

    hbdl_kernel<<<GRIDX, 256>>>(px, py, tgt, out);
}